// round 1
// baseline (speedup 1.0000x reference)
#include <cuda_runtime.h>
#include <cuda_bf16.h>
#include <math.h>

// ---------------- problem constants ----------------
#define B_   64
#define L_   192
#define LT_  8
#define S_   200
#define SP_  224      // padded seq rows (zeroed) so k=6 tap reads are in-bounds
#define C_   512
#define TD_  768
#define H_   8
#define D_   64
#define J_   22
#define QPAD 65

// ---------------- scratch (device globals; no allocation allowed) ----------------
__device__ float g_h  [B_ * C_ * L_];   // depthwise output, layout (b, c, l)
__device__ float g_xa [B_ * S_ * C_];   // concat [cond(8 rows) ; h(192 rows)] per batch
__device__ float g_att[B_ * L_ * C_];   // attention output rows s>=8 only
__device__ float g_z  [B_ * L_ * C_];   // w_out GEMM output
__device__ float g_h2 [B_ * L_ * C_];   // layernorm output

__device__ __forceinline__ float silu_f(float v) {
    return v / (1.f + expf(-v));
}

// ================= kernel 1: depthwise conv over joints + silu =================
// grid (C_, B_), 192 threads (= L). Lanes -> consecutive l -> contiguous 88B reads.
__global__ __launch_bounds__(192) void k_dw(const float* __restrict__ x,
                                            const float* __restrict__ dw_w,
                                            const float* __restrict__ dw_b,
                                            float* __restrict__ h) {
    int c = blockIdx.x, b = blockIdx.y, l = threadIdx.x;
    __shared__ float w[J_];
    __shared__ float bias;
    if (threadIdx.x < J_) w[threadIdx.x] = dw_w[c * J_ + threadIdx.x];
    if (threadIdx.x == 0) bias = dw_b[c];
    __syncthreads();
    const float2* xp = (const float2*)(x + (((size_t)b * C_ + c) * L_ + l) * J_);
    float s = bias;
#pragma unroll
    for (int j = 0; j < J_ / 2; j++) {
        float2 v = xp[j];
        s += v.x * w[2 * j] + v.y * w[2 * j + 1];
    }
    h[((size_t)b * C_ + c) * L_ + l] = silu_f(s);
}

// ================= kernel 2: pw GEMM (A is K-major per batch) =================
// out xa[b, 8+l, o] = sum_c h[b,c,l] * pw_w[o,c] + pw_b[o]
// grid (N/128=4, M/64=3, B), 256 threads, BM=64 BN=128 BK=8, 4x8 per thread.
__global__ __launch_bounds__(256) void k_gemm_pw(const float* __restrict__ A,
                                                 const float* __restrict__ W,
                                                 const float* __restrict__ bias,
                                                 float* __restrict__ xa) {
    __shared__ float As[8][64];
    __shared__ float Ws[8][128];
    int b = blockIdx.z, m0 = blockIdx.y * 64, n0 = blockIdx.x * 128;
    int tid = threadIdx.x;
    int kk = tid >> 5, mm = (tid & 31) * 2;
    const float* Ap = A + ((size_t)b * C_ + kk) * L_ + m0 + mm;
    int wrow = tid >> 1, wcol = (tid & 1) * 4;
    const float* Wp = W + (size_t)(n0 + wrow) * C_ + wcol;
    int tx = tid & 15, ty = tid >> 4;
    float acc[4][8];
#pragma unroll
    for (int i = 0; i < 4; i++)
#pragma unroll
        for (int j = 0; j < 8; j++) acc[i][j] = 0.f;

    for (int k0 = 0; k0 < C_; k0 += 8) {
        float2 av = *(const float2*)(Ap + (size_t)k0 * L_);
        float4 wv = *(const float4*)(Wp + k0);
        __syncthreads();
        *(float2*)&As[kk][mm] = av;
        Ws[wcol + 0][wrow] = wv.x; Ws[wcol + 1][wrow] = wv.y;
        Ws[wcol + 2][wrow] = wv.z; Ws[wcol + 3][wrow] = wv.w;
        __syncthreads();
#pragma unroll
        for (int k = 0; k < 8; k++) {
            float4 a0 = *(const float4*)&As[k][ty * 4];
            float4 b0 = *(const float4*)&Ws[k][tx * 8];
            float4 b1 = *(const float4*)&Ws[k][tx * 8 + 4];
            float a[4] = {a0.x, a0.y, a0.z, a0.w};
            float bb[8] = {b0.x, b0.y, b0.z, b0.w, b1.x, b1.y, b1.z, b1.w};
#pragma unroll
            for (int i = 0; i < 4; i++)
#pragma unroll
                for (int j = 0; j < 8; j++) acc[i][j] += a[i] * bb[j];
        }
    }
#pragma unroll
    for (int i = 0; i < 4; i++) {
        int row = b * S_ + LT_ + m0 + ty * 4 + i;
        float* op = xa + (size_t)row * C_ + n0 + tx * 8;
        float4 o0, o1;
        o0.x = acc[i][0] + bias[n0 + tx * 8 + 0];
        o0.y = acc[i][1] + bias[n0 + tx * 8 + 1];
        o0.z = acc[i][2] + bias[n0 + tx * 8 + 2];
        o0.w = acc[i][3] + bias[n0 + tx * 8 + 3];
        o1.x = acc[i][4] + bias[n0 + tx * 8 + 4];
        o1.y = acc[i][5] + bias[n0 + tx * 8 + 5];
        o1.z = acc[i][6] + bias[n0 + tx * 8 + 6];
        o1.w = acc[i][7] + bias[n0 + tx * 8 + 7];
        *(float4*)op = o0;
        *(float4*)(op + 4) = o1;
    }
}

// ================= generic NT GEMM: A row-major (M,K), W (N,K) row-major =================
// ACT: 0 none, 1 silu.  OMAP: 0 direct row m, 1 cond mapping ((m>>3)*200 + (m&7)).
template <int ACT, int OMAP>
__global__ __launch_bounds__(256) void k_gemm_nt(const float* __restrict__ A,
                                                 const float* __restrict__ W,
                                                 const float* __restrict__ bias,
                                                 float* __restrict__ out,
                                                 int K) {
    __shared__ float As[8][128];
    __shared__ float Ws[8][128];
    int m0 = blockIdx.y * 128, n0 = blockIdx.x * 128;
    int tid = threadIdx.x;
    int arow = tid >> 1, acol = (tid & 1) * 4;
    const float* Ap = A + (size_t)(m0 + arow) * K + acol;
    const float* Wp = W + (size_t)(n0 + arow) * K + acol;
    int tx = tid & 15, ty = tid >> 4;
    float acc[8][8];
#pragma unroll
    for (int i = 0; i < 8; i++)
#pragma unroll
        for (int j = 0; j < 8; j++) acc[i][j] = 0.f;

    for (int k0 = 0; k0 < K; k0 += 8) {
        float4 av = *(const float4*)(Ap + k0);
        float4 wv = *(const float4*)(Wp + k0);
        __syncthreads();
        As[acol + 0][arow] = av.x; As[acol + 1][arow] = av.y;
        As[acol + 2][arow] = av.z; As[acol + 3][arow] = av.w;
        Ws[acol + 0][arow] = wv.x; Ws[acol + 1][arow] = wv.y;
        Ws[acol + 2][arow] = wv.z; Ws[acol + 3][arow] = wv.w;
        __syncthreads();
#pragma unroll
        for (int k = 0; k < 8; k++) {
            float4 a0 = *(const float4*)&As[k][ty * 8];
            float4 a1 = *(const float4*)&As[k][ty * 8 + 4];
            float4 b0 = *(const float4*)&Ws[k][tx * 8];
            float4 b1 = *(const float4*)&Ws[k][tx * 8 + 4];
            float a[8] = {a0.x, a0.y, a0.z, a0.w, a1.x, a1.y, a1.z, a1.w};
            float bb[8] = {b0.x, b0.y, b0.z, b0.w, b1.x, b1.y, b1.z, b1.w};
#pragma unroll
            for (int i = 0; i < 8; i++)
#pragma unroll
                for (int j = 0; j < 8; j++) acc[i][j] += a[i] * bb[j];
        }
    }
#pragma unroll
    for (int i = 0; i < 8; i++) {
        int m = m0 + ty * 8 + i;
        size_t orow = (OMAP == 0) ? (size_t)m : (size_t)(m >> 3) * S_ + (m & 7);
        float* op = out + orow * C_ + n0 + tx * 8;
        float v[8];
#pragma unroll
        for (int j = 0; j < 8; j++) {
            float t = acc[i][j] + bias[n0 + tx * 8 + j];
            v[j] = (ACT == 1) ? silu_f(t) : t;
        }
        *(float4*)op = make_float4(v[0], v[1], v[2], v[3]);
        *(float4*)(op + 4) = make_float4(v[4], v[5], v[6], v[7]);
    }
}

// ================= kernel: fused self-attention, one CTA per (b,h) =================
// Q=K=V = xa slice (200 x 64). Computes only query rows i in [8,200).
__global__ __launch_bounds__(256) void k_attn(const float* __restrict__ xa,
                                              const float* __restrict__ rpe,
                                              float* __restrict__ att) {
    extern __shared__ float sm[];
    float(*q)[QPAD] = (float(*)[QPAD])sm;
    float* rp = sm + SP_ * QPAD;

    int h = blockIdx.x, b = blockIdx.y;
    int tid = threadIdx.x, lane = tid & 31, w = tid >> 5;

    // load Q tile (coalesced over d) and zero the pad rows
    {
        const float* base = xa + (size_t)b * S_ * C_ + h * D_;
        int d = tid & 63, s0 = tid >> 6;
        for (int s = s0; s < S_; s += 4) q[s][d] = base[(size_t)s * C_ + d];
        for (int s = S_ + s0; s < SP_; s += 4) q[s][d] = 0.f;
        for (int i = tid; i < 2 * S_ - 1; i += 256) rp[i] = rpe[h * (2 * S_ - 1) + i];
    }
    __syncthreads();

    // each warp: 24 query rows, processed 4 at a time
    for (int g = 0; g < 6; g++) {
        int i0 = LT_ + w * 24 + g * 4;
        float acc[4][7];
#pragma unroll
        for (int r = 0; r < 4; r++)
#pragma unroll
            for (int k = 0; k < 7; k++) acc[r][k] = 0.f;

        for (int dd = 0; dd < D_; dd++) {
            float a0 = q[i0 + 0][dd], a1 = q[i0 + 1][dd];
            float a2 = q[i0 + 2][dd], a3 = q[i0 + 3][dd];
#pragma unroll
            for (int k = 0; k < 7; k++) {
                float bb = q[lane + 32 * k][dd];
                acc[0][k] += a0 * bb; acc[1][k] += a1 * bb;
                acc[2][k] += a2 * bb; acc[3][k] += a3 * bb;
            }
        }

        float p[4][7];
#pragma unroll
        for (int r = 0; r < 4; r++) {
            int i = i0 + r;
            float mx = -1e30f;
#pragma unroll
            for (int k = 0; k < 7; k++) {
                int j = lane + 32 * k;
                float v = (j < S_) ? acc[r][k] * 0.125f + rp[j - i + (S_ - 1)] : -1e30f;
                p[r][k] = v;
                mx = fmaxf(mx, v);
            }
#pragma unroll
            for (int off = 16; off; off >>= 1)
                mx = fmaxf(mx, __shfl_xor_sync(0xffffffffu, mx, off));
            float sum = 0.f;
#pragma unroll
            for (int k = 0; k < 7; k++) {
                float e = expf(p[r][k] - mx);
                p[r][k] = e;
                sum += e;
            }
#pragma unroll
            for (int off = 16; off; off >>= 1)
                sum += __shfl_xor_sync(0xffffffffu, sum, off);
            float inv = 1.f / sum;
#pragma unroll
            for (int k = 0; k < 7; k++) p[r][k] *= inv;
        }

        // PV: out[d] = sum_j p[j] * q[j][d]; lane handles d=lane and d=lane+32
        float o00 = 0.f, o01 = 0.f, o10 = 0.f, o11 = 0.f;
        float o20 = 0.f, o21 = 0.f, o30 = 0.f, o31 = 0.f;
#pragma unroll
        for (int k = 0; k < 7; k++) {
            int jmax = (k == 6) ? 8 : 32;
            for (int src = 0; src < jmax; src++) {
                int j = 32 * k + src;
                float b0 = q[j][lane];
                float b1 = q[j][lane + 32];
                float p0 = __shfl_sync(0xffffffffu, p[0][k], src);
                float p1 = __shfl_sync(0xffffffffu, p[1][k], src);
                float p2 = __shfl_sync(0xffffffffu, p[2][k], src);
                float p3 = __shfl_sync(0xffffffffu, p[3][k], src);
                o00 += p0 * b0; o01 += p0 * b1;
                o10 += p1 * b0; o11 += p1 * b1;
                o20 += p2 * b0; o21 += p2 * b1;
                o30 += p3 * b0; o31 += p3 * b1;
            }
        }
        float* ob = att + ((size_t)b * L_ + (i0 - LT_)) * C_ + h * D_;
        ob[0 * C_ + lane] = o00; ob[0 * C_ + lane + 32] = o01;
        ob[1 * C_ + lane] = o10; ob[1 * C_ + lane + 32] = o11;
        ob[2 * C_ + lane] = o20; ob[2 * C_ + lane + 32] = o21;
        ob[3 * C_ + lane] = o30; ob[3 * C_ + lane + 32] = o31;
    }
}

// ================= kernel: residual add + layernorm =================
__device__ __forceinline__ float block_sum256(float v, float* red) {
    __syncthreads();  // make smem reusable across calls
#pragma unroll
    for (int o = 16; o; o >>= 1) v += __shfl_xor_sync(0xffffffffu, v, o);
    int w = threadIdx.x >> 5;
    if ((threadIdx.x & 31) == 0) red[w] = v;
    __syncthreads();
    if (w == 0) {
        float x = ((threadIdx.x & 31) < 8) ? red[threadIdx.x & 31] : 0.f;
#pragma unroll
        for (int o = 4; o; o >>= 1) x += __shfl_xor_sync(0xffffffffu, x, o);
        if (threadIdx.x == 0) red[0] = x;
    }
    __syncthreads();
    return red[0];
}

__global__ __launch_bounds__(256) void k_ln(const float* __restrict__ z,
                                            const float* __restrict__ xa,
                                            const float* __restrict__ gamma,
                                            const float* __restrict__ beta,
                                            float* __restrict__ h2) {
    __shared__ float red[8];
    int m = blockIdx.x;
    int b = m / L_, l = m % L_;
    const float* zr = z + (size_t)m * C_;
    const float* rr = xa + ((size_t)b * S_ + LT_ + l) * C_;
    int t = threadIdx.x;
    float v0 = zr[t] + rr[t];
    float v1 = zr[t + 256] + rr[t + 256];
    float s = block_sum256(v0 + v1, red);
    float mu = s * (1.f / (float)C_);
    float d0 = v0 - mu, d1 = v1 - mu;
    float vs = block_sum256(d0 * d0 + d1 * d1, red);
    float rstd = rsqrtf(vs * (1.f / (float)C_) + 1e-5f);
    h2[(size_t)m * C_ + t] = d0 * rstd * gamma[t] + beta[t];
    h2[(size_t)m * C_ + t + 256] = d1 * rstd * gamma[t + 256] + beta[t + 256];
}

// ================= launch =================
extern "C" void kernel_launch(void* const* d_in, const int* in_sizes, int n_in,
                              void* d_out, int out_size) {
    const float* x         = (const float*)d_in[0];
    const float* text_emb1 = (const float*)d_in[2];
    const float* dw_w      = (const float*)d_in[6];
    const float* dw_b      = (const float*)d_in[7];
    const float* pw_w      = (const float*)d_in[8];
    const float* pw_b      = (const float*)d_in[9];
    const float* wt        = (const float*)d_in[10];
    const float* bt        = (const float*)d_in[11];
    const float* rpe       = (const float*)d_in[12];
    const float* w_out     = (const float*)d_in[13];
    const float* b_out     = (const float*)d_in[14];
    const float* ln_g      = (const float*)d_in[15];
    const float* ln_b      = (const float*)d_in[16];
    const float* wp        = (const float*)d_in[17];
    const float* bp        = (const float*)d_in[18];
    float* out = (float*)d_out;

    float *p_h, *p_xa, *p_att, *p_z, *p_h2;
    cudaGetSymbolAddress((void**)&p_h, g_h);
    cudaGetSymbolAddress((void**)&p_xa, g_xa);
    cudaGetSymbolAddress((void**)&p_att, g_att);
    cudaGetSymbolAddress((void**)&p_z, g_z);
    cudaGetSymbolAddress((void**)&p_h2, g_h2);

    // 1. depthwise + silu -> g_h (b,c,l)
    k_dw<<<dim3(C_, B_), 192>>>(x, dw_w, dw_b, p_h);

    // 2. pointwise GEMM -> xa rows [8,200)
    k_gemm_pw<<<dim3(4, 3, B_), 256>>>(p_h, pw_w, pw_b, p_xa);

    // 3. cond GEMM + silu -> xa rows [0,8)
    k_gemm_nt<1, 1><<<dim3(4, 4), 256>>>(text_emb1, wt, bt, p_xa, TD_);

    // 4. attention (query rows >= 8 only)
    int smem = SP_ * QPAD * sizeof(float) + 2 * S_ * sizeof(float);
    cudaFuncSetAttribute(k_attn, cudaFuncAttributeMaxDynamicSharedMemorySize, smem);
    k_attn<<<dim3(H_, B_), 256, smem>>>(p_xa, rpe, p_att);

    // 5. output projection
    k_gemm_nt<0, 0><<<dim3(4, 96), 256>>>(p_att, w_out, b_out, p_z, C_);

    // 6. residual + layernorm
    k_ln<<<B_ * L_, 256>>>(p_z, p_xa, ln_g, ln_b, p_h2);

    // 7. final projection + silu -> out
    k_gemm_nt<1, 0><<<dim3(4, 96), 256>>>(p_h2, wp, bp, out, C_);

    (void)in_sizes; (void)n_in; (void)out_size;
}

// round 5
// speedup vs baseline: 2.1259x; 2.1259x over previous
#include <cuda_runtime.h>
#include <cuda_bf16.h>
#include <math.h>
#include <stdint.h>

// ---------------- problem constants ----------------
#define B_   64
#define L_   192
#define LT_  8
#define S_   200
#define SP_  224
#define C_   512
#define TD_  768
#define H_   8
#define D_   64
#define J_   22
#define QPAD 65
#define M_   (B_ * L_)   // 12288

// ---------------- scratch ----------------
__device__ float g_ht [C_ * M_];        // depthwise output, K-major: [c][b*192+l]
__device__ float g_xa [B_ * S_ * C_];   // concat [cond(8) ; h(192)] per batch
__device__ float g_att[B_ * L_ * C_];
__device__ float g_z  [B_ * L_ * C_];
__device__ float g_h2 [B_ * L_ * C_];

__device__ __forceinline__ float silu_f(float v) { return v / (1.f + expf(-v)); }

__device__ __forceinline__ unsigned int f2tf32(float f) {
    unsigned int r;
    asm("cvt.rna.tf32.f32 %0, %1;" : "=r"(r) : "f"(f));
    return r;
}
__device__ __forceinline__ float4 cvt4(float4 v) {
    v.x = __uint_as_float(f2tf32(v.x));
    v.y = __uint_as_float(f2tf32(v.y));
    v.z = __uint_as_float(f2tf32(v.z));
    v.w = __uint_as_float(f2tf32(v.w));
    return v;
}
__device__ __forceinline__ void mma8(float* d, const unsigned int* a, const unsigned int* b) {
    asm volatile(
        "mma.sync.aligned.m16n8k8.row.col.f32.tf32.tf32.f32 "
        "{%0,%1,%2,%3}, {%4,%5,%6,%7}, {%8,%9}, {%0,%1,%2,%3};"
        : "+f"(d[0]), "+f"(d[1]), "+f"(d[2]), "+f"(d[3])
        : "r"(a[0]), "r"(a[1]), "r"(a[2]), "r"(a[3]), "r"(b[0]), "r"(b[1]));
}

// ================= kernel 1: depthwise conv + silu, K-major output =================
__global__ __launch_bounds__(192) void k_dw(const float* __restrict__ x,
                                            const float* __restrict__ dw_w,
                                            const float* __restrict__ dw_b,
                                            float* __restrict__ ht) {
    int c = blockIdx.x, b = blockIdx.y, l = threadIdx.x;
    __shared__ float w[J_];
    __shared__ float bias;
    if (threadIdx.x < J_) w[threadIdx.x] = dw_w[c * J_ + threadIdx.x];
    if (threadIdx.x == 0) bias = dw_b[c];
    __syncthreads();
    const float2* xp = (const float2*)(x + (((size_t)b * C_ + c) * L_ + l) * J_);
    float s = bias;
#pragma unroll
    for (int j = 0; j < J_ / 2; j++) {
        float2 v = xp[j];
        s += v.x * w[2 * j] + v.y * w[2 * j + 1];
    }
    ht[(size_t)c * M_ + b * L_ + l] = silu_f(s);
}

// ================= tf32 tensor-core GEMM =================
// out[omap(m)][n] = act( sum_k A(m,k) * W[n][k] + bias[n] )
// AKM: 0 -> A row-major (M,K) lda=K ;  1 -> A K-major (K,M) lda=M
// ACT: 0 none, 1 silu
// OMAP: 0 direct ; 1 cond (m -> (m>>3)*200 + (m&7)) ; 2 pw (m -> (m/192)*200 + 8 + m%192)
#define BM 128
#define BN 128
#define BK 32
#define LDA_RM 36   // As[m][k] pad
#define LDA_KM 132  // As[k][m] pad
#define LDB    36

template <int AKM, int ACT, int OMAP>
__global__ __launch_bounds__(256) void k_mm(const float* __restrict__ A,
                                            const float* __restrict__ W,
                                            const float* __restrict__ bias,
                                            float* __restrict__ out,
                                            int K, int lda) {
    __shared__ float As[BM * LDA_RM];  // 4608 floats (covers both layouts)
    __shared__ float Ws[BN * LDB];

    const int tid = threadIdx.x;
    const int lane = tid & 31, wid = tid >> 5;
    const int warp_m = (wid & 1) * 64;   // 2 warps along M
    const int warp_n = (wid >> 1) * 32;  // 4 warps along N
    const int m0 = blockIdx.y * BM, n0 = blockIdx.x * BN;

    float acc[4][4][4];
#pragma unroll
    for (int i = 0; i < 4; i++)
#pragma unroll
        for (int j = 0; j < 4; j++)
#pragma unroll
            for (int r = 0; r < 4; r++) acc[i][j][r] = 0.f;

    // global-load thread mappings
    const int grow = tid >> 3, gcol = (tid & 7) * 4;
    const int kmc = (tid & 31) * 4, kkr = tid >> 5;

    float4 stA[4], stW[4];
    // prefetch k0 = 0
    if (AKM == 0) {
#pragma unroll
        for (int i = 0; i < 4; i++)
            stA[i] = *(const float4*)(A + (size_t)(m0 + grow + 32 * i) * lda + gcol);
    } else {
#pragma unroll
        for (int i = 0; i < 4; i++)
            stA[i] = *(const float4*)(A + (size_t)(kkr + 8 * i) * lda + m0 + kmc);
    }
#pragma unroll
    for (int i = 0; i < 4; i++)
        stW[i] = *(const float4*)(W + (size_t)(n0 + grow + 32 * i) * K + gcol);

    for (int k0 = 0; k0 < K; k0 += BK) {
        __syncthreads();
        // store staged tile (converted to tf32)
        if (AKM == 0) {
#pragma unroll
            for (int i = 0; i < 4; i++)
                *(float4*)&As[(grow + 32 * i) * LDA_RM + gcol] = cvt4(stA[i]);
        } else {
#pragma unroll
            for (int i = 0; i < 4; i++)
                *(float4*)&As[(kkr + 8 * i) * LDA_KM + kmc] = cvt4(stA[i]);
        }
#pragma unroll
        for (int i = 0; i < 4; i++)
            *(float4*)&Ws[(grow + 32 * i) * LDB + gcol] = cvt4(stW[i]);
        __syncthreads();

        // prefetch next tile
        if (k0 + BK < K) {
            if (AKM == 0) {
#pragma unroll
                for (int i = 0; i < 4; i++)
                    stA[i] = *(const float4*)(A + (size_t)(m0 + grow + 32 * i) * lda + k0 + BK + gcol);
            } else {
#pragma unroll
                for (int i = 0; i < 4; i++)
                    stA[i] = *(const float4*)(A + (size_t)(k0 + BK + kkr + 8 * i) * lda + m0 + kmc);
            }
#pragma unroll
            for (int i = 0; i < 4; i++)
                stW[i] = *(const float4*)(W + (size_t)(n0 + grow + 32 * i) * K + k0 + BK + gcol);
        }

        // compute 4 k-steps of m16n8k8
#pragma unroll
        for (int ks = 0; ks < 4; ks++) {
            const int col = ks * 8 + (lane & 3);
            unsigned int afr[4][4], bfr[4][2];
#pragma unroll
            for (int mt = 0; mt < 4; mt++) {
                int row = warp_m + mt * 16 + (lane >> 2);
                if (AKM == 0) {
                    afr[mt][0] = __float_as_uint(As[row * LDA_RM + col]);
                    afr[mt][1] = __float_as_uint(As[(row + 8) * LDA_RM + col]);
                    afr[mt][2] = __float_as_uint(As[row * LDA_RM + col + 4]);
                    afr[mt][3] = __float_as_uint(As[(row + 8) * LDA_RM + col + 4]);
                } else {
                    afr[mt][0] = __float_as_uint(As[col * LDA_KM + row]);
                    afr[mt][1] = __float_as_uint(As[col * LDA_KM + row + 8]);
                    afr[mt][2] = __float_as_uint(As[(col + 4) * LDA_KM + row]);
                    afr[mt][3] = __float_as_uint(As[(col + 4) * LDA_KM + row + 8]);
                }
            }
#pragma unroll
            for (int nt = 0; nt < 4; nt++) {
                int nrow = warp_n + nt * 8 + (lane >> 2);
                bfr[nt][0] = __float_as_uint(Ws[nrow * LDB + col]);
                bfr[nt][1] = __float_as_uint(Ws[nrow * LDB + col + 4]);
            }
#pragma unroll
            for (int mt = 0; mt < 4; mt++)
#pragma unroll
                for (int nt = 0; nt < 4; nt++)
                    mma8(acc[mt][nt], afr[mt], bfr[nt]);
        }
    }

    // epilogue
#pragma unroll
    for (int nt = 0; nt < 4; nt++) {
        const int n = n0 + warp_n + nt * 8 + (lane & 3) * 2;
        const float bi0 = bias[n], bi1 = bias[n + 1];
#pragma unroll
        for (int mt = 0; mt < 4; mt++) {
            int m = m0 + warp_m + mt * 16 + (lane >> 2);
#pragma unroll
            for (int half = 0; half < 2; half++) {
                int mm = m + half * 8;
                size_t orow;
                if (OMAP == 0) orow = (size_t)mm;
                else if (OMAP == 1) orow = (size_t)(mm >> 3) * S_ + (mm & 7);
                else orow = (size_t)(mm / L_) * S_ + LT_ + (mm % L_);
                float v0 = acc[mt][nt][half * 2 + 0] + bi0;
                float v1 = acc[mt][nt][half * 2 + 1] + bi1;
                if (ACT == 1) { v0 = silu_f(v0); v1 = silu_f(v1); }
                float2* op = (float2*)(out + orow * C_ + n);
                *op = make_float2(v0, v1);
            }
        }
    }
}

// ================= fused self-attention =================
__global__ __launch_bounds__(256) void k_attn(const float* __restrict__ xa,
                                              const float* __restrict__ rpe,
                                              float* __restrict__ att) {
    extern __shared__ float sm[];
    float(*q)[QPAD] = (float(*)[QPAD])sm;
    float* rp = sm + SP_ * QPAD;

    int h = blockIdx.x, b = blockIdx.y;
    int tid = threadIdx.x, lane = tid & 31, w = tid >> 5;

    {
        const float* base = xa + (size_t)b * S_ * C_ + h * D_;
        int d = tid & 63, s0 = tid >> 6;
        for (int s = s0; s < S_; s += 4) q[s][d] = base[(size_t)s * C_ + d];
        for (int s = S_ + s0; s < SP_; s += 4) q[s][d] = 0.f;
        for (int i = tid; i < 2 * S_ - 1; i += 256) rp[i] = rpe[h * (2 * S_ - 1) + i];
    }
    __syncthreads();

    for (int g = 0; g < 6; g++) {
        int i0 = LT_ + w * 24 + g * 4;
        float acc[4][7];
#pragma unroll
        for (int r = 0; r < 4; r++)
#pragma unroll
            for (int k = 0; k < 7; k++) acc[r][k] = 0.f;

        for (int dd = 0; dd < D_; dd++) {
            float a0 = q[i0 + 0][dd], a1 = q[i0 + 1][dd];
            float a2 = q[i0 + 2][dd], a3 = q[i0 + 3][dd];
#pragma unroll
            for (int k = 0; k < 7; k++) {
                float bb = q[lane + 32 * k][dd];
                acc[0][k] += a0 * bb; acc[1][k] += a1 * bb;
                acc[2][k] += a2 * bb; acc[3][k] += a3 * bb;
            }
        }

        float p[4][7];
#pragma unroll
        for (int r = 0; r < 4; r++) {
            int i = i0 + r;
            float mx = -1e30f;
#pragma unroll
            for (int k = 0; k < 7; k++) {
                int j = lane + 32 * k;
                float v = (j < S_) ? acc[r][k] * 0.125f + rp[j - i + (S_ - 1)] : -1e30f;
                p[r][k] = v;
                mx = fmaxf(mx, v);
            }
#pragma unroll
            for (int off = 16; off; off >>= 1)
                mx = fmaxf(mx, __shfl_xor_sync(0xffffffffu, mx, off));
            float sum = 0.f;
#pragma unroll
            for (int k = 0; k < 7; k++) {
                float e = expf(p[r][k] - mx);
                p[r][k] = e;
                sum += e;
            }
#pragma unroll
            for (int off = 16; off; off >>= 1)
                sum += __shfl_xor_sync(0xffffffffu, sum, off);
            float inv = 1.f / sum;
#pragma unroll
            for (int k = 0; k < 7; k++) p[r][k] *= inv;
        }

        float o00 = 0.f, o01 = 0.f, o10 = 0.f, o11 = 0.f;
        float o20 = 0.f, o21 = 0.f, o30 = 0.f, o31 = 0.f;
#pragma unroll
        for (int k = 0; k < 7; k++) {
            int jmax = (k == 6) ? 8 : 32;
            for (int src = 0; src < jmax; src++) {
                int j = 32 * k + src;
                float b0 = q[j][lane];
                float b1 = q[j][lane + 32];
                float p0 = __shfl_sync(0xffffffffu, p[0][k], src);
                float p1 = __shfl_sync(0xffffffffu, p[1][k], src);
                float p2 = __shfl_sync(0xffffffffu, p[2][k], src);
                float p3 = __shfl_sync(0xffffffffu, p[3][k], src);
                o00 += p0 * b0; o01 += p0 * b1;
                o10 += p1 * b0; o11 += p1 * b1;
                o20 += p2 * b0; o21 += p2 * b1;
                o30 += p3 * b0; o31 += p3 * b1;
            }
        }
        float* ob = att + ((size_t)b * L_ + (i0 - LT_)) * C_ + h * D_;
        ob[0 * C_ + lane] = o00; ob[0 * C_ + lane + 32] = o01;
        ob[1 * C_ + lane] = o10; ob[1 * C_ + lane + 32] = o11;
        ob[2 * C_ + lane] = o20; ob[2 * C_ + lane + 32] = o21;
        ob[3 * C_ + lane] = o30; ob[3 * C_ + lane + 32] = o31;
    }
}

// ================= residual + layernorm =================
__device__ __forceinline__ float block_sum256(float v, float* red) {
    __syncthreads();
#pragma unroll
    for (int o = 16; o; o >>= 1) v += __shfl_xor_sync(0xffffffffu, v, o);
    int w = threadIdx.x >> 5;
    if ((threadIdx.x & 31) == 0) red[w] = v;
    __syncthreads();
    if (w == 0) {
        float x = ((threadIdx.x & 31) < 8) ? red[threadIdx.x & 31] : 0.f;
#pragma unroll
        for (int o = 4; o; o >>= 1) x += __shfl_xor_sync(0xffffffffu, x, o);
        if (threadIdx.x == 0) red[0] = x;
    }
    __syncthreads();
    return red[0];
}

__global__ __launch_bounds__(256) void k_ln(const float* __restrict__ z,
                                            const float* __restrict__ xa,
                                            const float* __restrict__ gamma,
                                            const float* __restrict__ beta,
                                            float* __restrict__ h2) {
    __shared__ float red[8];
    int m = blockIdx.x;
    int b = m / L_, l = m % L_;
    const float* zr = z + (size_t)m * C_;
    const float* rr = xa + ((size_t)b * S_ + LT_ + l) * C_;
    int t = threadIdx.x;
    float v0 = zr[t] + rr[t];
    float v1 = zr[t + 256] + rr[t + 256];
    float s = block_sum256(v0 + v1, red);
    float mu = s * (1.f / (float)C_);
    float d0 = v0 - mu, d1 = v1 - mu;
    float vs = block_sum256(d0 * d0 + d1 * d1, red);
    float rstd = rsqrtf(vs * (1.f / (float)C_) + 1e-5f);
    h2[(size_t)m * C_ + t] = d0 * rstd * gamma[t] + beta[t];
    h2[(size_t)m * C_ + t + 256] = d1 * rstd * gamma[t + 256] + beta[t + 256];
}

// ================= launch =================
extern "C" void kernel_launch(void* const* d_in, const int* in_sizes, int n_in,
                              void* d_out, int out_size) {
    const float* x         = (const float*)d_in[0];
    const float* text_emb1 = (const float*)d_in[2];
    const float* dw_w      = (const float*)d_in[6];
    const float* dw_b      = (const float*)d_in[7];
    const float* pw_w      = (const float*)d_in[8];
    const float* pw_b      = (const float*)d_in[9];
    const float* wt        = (const float*)d_in[10];
    const float* bt        = (const float*)d_in[11];
    const float* rpe       = (const float*)d_in[12];
    const float* w_out     = (const float*)d_in[13];
    const float* b_out     = (const float*)d_in[14];
    const float* ln_g      = (const float*)d_in[15];
    const float* ln_b      = (const float*)d_in[16];
    const float* wp        = (const float*)d_in[17];
    const float* bp        = (const float*)d_in[18];
    float* out = (float*)d_out;

    float *p_ht, *p_xa, *p_att, *p_z, *p_h2;
    cudaGetSymbolAddress((void**)&p_ht, g_ht);
    cudaGetSymbolAddress((void**)&p_xa, g_xa);
    cudaGetSymbolAddress((void**)&p_att, g_att);
    cudaGetSymbolAddress((void**)&p_z, g_z);
    cudaGetSymbolAddress((void**)&p_h2, g_h2);

    // 1. depthwise + silu -> g_ht (K-major: [c][b*192+l])
    k_dw<<<dim3(C_, B_), 192>>>(x, dw_w, dw_b, p_ht);

    // 2. pointwise GEMM (A K-major) -> xa rows [8,200)
    k_mm<1, 0, 2><<<dim3(4, M_ / BM), 256>>>(p_ht, pw_w, pw_b, p_xa, C_, M_);

    // 3. cond GEMM + silu -> xa rows [0,8)
    k_mm<0, 1, 1><<<dim3(4, 4), 256>>>(text_emb1, wt, bt, p_xa, TD_, TD_);

    // 4. attention
    int smem = SP_ * QPAD * sizeof(float) + 2 * S_ * sizeof(float);
    cudaFuncSetAttribute(k_attn, cudaFuncAttributeMaxDynamicSharedMemorySize, smem);
    k_attn<<<dim3(H_, B_), 256, smem>>>(p_xa, rpe, p_att);

    // 5. output projection
    k_mm<0, 0, 0><<<dim3(4, M_ / BM), 256>>>(p_att, w_out, b_out, p_z, C_, C_);

    // 6. residual + layernorm
    k_ln<<<B_ * L_, 256>>>(p_z, p_xa, ln_g, ln_b, p_h2);

    // 7. final projection + silu -> out
    k_mm<0, 1, 0><<<dim3(4, M_ / BM), 256>>>(p_h2, wp, bp, out, C_, C_);

    (void)in_sizes; (void)n_in; (void)out_size;
}

// round 6
// speedup vs baseline: 2.6527x; 1.2478x over previous
#include <cuda_runtime.h>
#include <cuda_bf16.h>
#include <math.h>
#include <stdint.h>

// ---------------- problem constants ----------------
#define B_   64
#define L_   192
#define LT_  8
#define S_   200
#define C_   512
#define TD_  768
#define H_   8
#define D_   64
#define J_   22
#define M_   (B_ * L_)   // 12288

// ---------------- scratch ----------------
__device__ float g_ht [C_ * M_];        // depthwise output, K-major: [c][b*192+l]
__device__ float g_xa [B_ * S_ * C_];   // concat [cond(8) ; h(192)] per batch
__device__ float g_att[B_ * L_ * C_];
__device__ float g_z  [B_ * L_ * C_];
__device__ float g_h2 [B_ * L_ * C_];

__device__ __forceinline__ float silu_f(float v) { return v / (1.f + expf(-v)); }

__device__ __forceinline__ unsigned int f2tf32(float f) {
    unsigned int r;
    asm("cvt.rna.tf32.f32 %0, %1;" : "=r"(r) : "f"(f));
    return r;
}
__device__ __forceinline__ float4 cvt4(float4 v) {
    v.x = __uint_as_float(f2tf32(v.x));
    v.y = __uint_as_float(f2tf32(v.y));
    v.z = __uint_as_float(f2tf32(v.z));
    v.w = __uint_as_float(f2tf32(v.w));
    return v;
}
__device__ __forceinline__ void mma8(float* d, const unsigned int* a, const unsigned int* b) {
    asm volatile(
        "mma.sync.aligned.m16n8k8.row.col.f32.tf32.tf32.f32 "
        "{%0,%1,%2,%3}, {%4,%5,%6,%7}, {%8,%9}, {%0,%1,%2,%3};"
        : "+f"(d[0]), "+f"(d[1]), "+f"(d[2]), "+f"(d[3])
        : "r"(a[0]), "r"(a[1]), "r"(a[2]), "r"(a[3]), "r"(b[0]), "r"(b[1]));
}

// ================= kernel 1: depthwise conv + silu, K-major output =================
__global__ __launch_bounds__(192) void k_dw(const float* __restrict__ x,
                                            const float* __restrict__ dw_w,
                                            const float* __restrict__ dw_b,
                                            float* __restrict__ ht) {
    int c = blockIdx.x, b = blockIdx.y, l = threadIdx.x;
    __shared__ float w[J_];
    __shared__ float bias;
    if (threadIdx.x < J_) w[threadIdx.x] = dw_w[c * J_ + threadIdx.x];
    if (threadIdx.x == 0) bias = dw_b[c];
    __syncthreads();
    const float2* xp = (const float2*)(x + (((size_t)b * C_ + c) * L_ + l) * J_);
    float s = bias;
#pragma unroll
    for (int j = 0; j < J_ / 2; j++) {
        float2 v = xp[j];
        s += v.x * w[2 * j] + v.y * w[2 * j + 1];
    }
    ht[(size_t)c * M_ + b * L_ + l] = silu_f(s);
}

// ================= tf32 tensor-core GEMM (unchanged from R5) =================
#define BM 128
#define BN 128
#define BK 32
#define LDA_RM 36
#define LDA_KM 132
#define LDB    36

template <int AKM, int ACT, int OMAP>
__global__ __launch_bounds__(256) void k_mm(const float* __restrict__ A,
                                            const float* __restrict__ W,
                                            const float* __restrict__ bias,
                                            float* __restrict__ out,
                                            int K, int lda) {
    __shared__ float As[BM * LDA_RM];
    __shared__ float Ws[BN * LDB];

    const int tid = threadIdx.x;
    const int lane = tid & 31, wid = tid >> 5;
    const int warp_m = (wid & 1) * 64;
    const int warp_n = (wid >> 1) * 32;
    const int m0 = blockIdx.y * BM, n0 = blockIdx.x * BN;

    float acc[4][4][4];
#pragma unroll
    for (int i = 0; i < 4; i++)
#pragma unroll
        for (int j = 0; j < 4; j++)
#pragma unroll
            for (int r = 0; r < 4; r++) acc[i][j][r] = 0.f;

    const int grow = tid >> 3, gcol = (tid & 7) * 4;
    const int kmc = (tid & 31) * 4, kkr = tid >> 5;

    float4 stA[4], stW[4];
    if (AKM == 0) {
#pragma unroll
        for (int i = 0; i < 4; i++)
            stA[i] = *(const float4*)(A + (size_t)(m0 + grow + 32 * i) * lda + gcol);
    } else {
#pragma unroll
        for (int i = 0; i < 4; i++)
            stA[i] = *(const float4*)(A + (size_t)(kkr + 8 * i) * lda + m0 + kmc);
    }
#pragma unroll
    for (int i = 0; i < 4; i++)
        stW[i] = *(const float4*)(W + (size_t)(n0 + grow + 32 * i) * K + gcol);

    for (int k0 = 0; k0 < K; k0 += BK) {
        __syncthreads();
        if (AKM == 0) {
#pragma unroll
            for (int i = 0; i < 4; i++)
                *(float4*)&As[(grow + 32 * i) * LDA_RM + gcol] = cvt4(stA[i]);
        } else {
#pragma unroll
            for (int i = 0; i < 4; i++)
                *(float4*)&As[(kkr + 8 * i) * LDA_KM + kmc] = cvt4(stA[i]);
        }
#pragma unroll
        for (int i = 0; i < 4; i++)
            *(float4*)&Ws[(grow + 32 * i) * LDB + gcol] = cvt4(stW[i]);
        __syncthreads();

        if (k0 + BK < K) {
            if (AKM == 0) {
#pragma unroll
                for (int i = 0; i < 4; i++)
                    stA[i] = *(const float4*)(A + (size_t)(m0 + grow + 32 * i) * lda + k0 + BK + gcol);
            } else {
#pragma unroll
                for (int i = 0; i < 4; i++)
                    stA[i] = *(const float4*)(A + (size_t)(k0 + BK + kkr + 8 * i) * lda + m0 + kmc);
            }
#pragma unroll
            for (int i = 0; i < 4; i++)
                stW[i] = *(const float4*)(W + (size_t)(n0 + grow + 32 * i) * K + k0 + BK + gcol);
        }

#pragma unroll
        for (int ks = 0; ks < 4; ks++) {
            const int col = ks * 8 + (lane & 3);
            unsigned int afr[4][4], bfr[4][2];
#pragma unroll
            for (int mt = 0; mt < 4; mt++) {
                int row = warp_m + mt * 16 + (lane >> 2);
                if (AKM == 0) {
                    afr[mt][0] = __float_as_uint(As[row * LDA_RM + col]);
                    afr[mt][1] = __float_as_uint(As[(row + 8) * LDA_RM + col]);
                    afr[mt][2] = __float_as_uint(As[row * LDA_RM + col + 4]);
                    afr[mt][3] = __float_as_uint(As[(row + 8) * LDA_RM + col + 4]);
                } else {
                    afr[mt][0] = __float_as_uint(As[col * LDA_KM + row]);
                    afr[mt][1] = __float_as_uint(As[col * LDA_KM + row + 8]);
                    afr[mt][2] = __float_as_uint(As[(col + 4) * LDA_KM + row]);
                    afr[mt][3] = __float_as_uint(As[(col + 4) * LDA_KM + row + 8]);
                }
            }
#pragma unroll
            for (int nt = 0; nt < 4; nt++) {
                int nrow = warp_n + nt * 8 + (lane >> 2);
                bfr[nt][0] = __float_as_uint(Ws[nrow * LDB + col]);
                bfr[nt][1] = __float_as_uint(Ws[nrow * LDB + col + 4]);
            }
#pragma unroll
            for (int mt = 0; mt < 4; mt++)
#pragma unroll
                for (int nt = 0; nt < 4; nt++)
                    mma8(acc[mt][nt], afr[mt], bfr[nt]);
        }
    }

#pragma unroll
    for (int nt = 0; nt < 4; nt++) {
        const int n = n0 + warp_n + nt * 8 + (lane & 3) * 2;
        const float bi0 = bias[n], bi1 = bias[n + 1];
#pragma unroll
        for (int mt = 0; mt < 4; mt++) {
            int m = m0 + warp_m + mt * 16 + (lane >> 2);
#pragma unroll
            for (int half = 0; half < 2; half++) {
                int mm = m + half * 8;
                size_t orow;
                if (OMAP == 0) orow = (size_t)mm;
                else if (OMAP == 1) orow = (size_t)(mm >> 3) * S_ + (mm & 7);
                else orow = (size_t)(mm / L_) * S_ + LT_ + (mm % L_);
                float v0 = acc[mt][nt][half * 2 + 0] + bi0;
                float v1 = acc[mt][nt][half * 2 + 1] + bi1;
                if (ACT == 1) { v0 = silu_f(v0); v1 = silu_f(v1); }
                float2* op = (float2*)(out + orow * C_ + n);
                *op = make_float2(v0, v1);
            }
        }
    }
}

// ================= tensor-core attention =================
// grid (2, H, B), 192 threads (6 warps). CTA handles 96 query rows (half).
// Q=K=V tile (208x64, tf32) in smem; per-warp score slab 16x212; warp softmax.
#define QLD 68    // 68%32==4 -> A/B fragment LDS conflict-free
#define PLD 212   // 212%32==20 -> P fragment LDS conflict-free
#define SPAD 208  // padded seq (26 j-tiles of 8)
#define NJT 26

__global__ __launch_bounds__(192) void k_attn_mma(const float* __restrict__ xa,
                                                  const float* __restrict__ rpe,
                                                  float* __restrict__ att) {
    extern __shared__ float sm[];
    float* Qs = sm;                      // [208][QLD]
    float* Ps = sm + SPAD * QLD;         // [6][16][PLD]
    float* rp = Ps + 6 * 16 * PLD;       // [399]

    const int half = blockIdx.x, h = blockIdx.y, b = blockIdx.z;
    const int tid = threadIdx.x, lane = tid & 31, w = tid >> 5;
    const int r = lane >> 2, c = lane & 3;

    // stage Q (tf32) + rpe
    {
        const float* base = xa + (size_t)b * S_ * C_ + h * D_;
        int d = tid & 63;
        for (int s = tid >> 6; s < SPAD; s += 3) {
            float v = (s < S_) ? base[(size_t)s * C_ + d] : 0.f;
            Qs[s * QLD + d] = __uint_as_float(f2tf32(v));
        }
        for (int i = tid; i < 2 * S_ - 1; i += 192) rp[i] = rpe[h * (2 * S_ - 1) + i];
    }
    __syncthreads();

    const int i0 = LT_ + half * 96 + w * 16;
    float* Pw = Ps + w * 16 * PLD;

    // ---- QK^T: 16 rows x 208 cols ----
    unsigned int afr[8][4];
#pragma unroll
    for (int k = 0; k < 8; k++) {
        afr[k][0] = __float_as_uint(Qs[(i0 + r) * QLD + k * 8 + c]);
        afr[k][1] = __float_as_uint(Qs[(i0 + r + 8) * QLD + k * 8 + c]);
        afr[k][2] = __float_as_uint(Qs[(i0 + r) * QLD + k * 8 + c + 4]);
        afr[k][3] = __float_as_uint(Qs[(i0 + r + 8) * QLD + k * 8 + c + 4]);
    }
#pragma unroll
    for (int nt = 0; nt < NJT; nt++) {
        const int j0 = nt * 8;
        float acc[4] = {0.f, 0.f, 0.f, 0.f};
#pragma unroll
        for (int k = 0; k < 8; k++) {
            unsigned int bfr[2];
            bfr[0] = __float_as_uint(Qs[(j0 + r) * QLD + k * 8 + c]);
            bfr[1] = __float_as_uint(Qs[(j0 + r) * QLD + k * 8 + c + 4]);
            mma8(acc, afr[k], bfr);
        }
        const int j = j0 + 2 * c;
        if (nt < 25) {  // j, j+1 < 200 always here
            const int i_lo = i0 + r, i_hi = i_lo + 8;
            float r0 = rp[j - i_lo + (S_ - 1)], r1 = rp[j + 1 - i_lo + (S_ - 1)];
            float r2 = rp[j - i_hi + (S_ - 1)], r3 = rp[j + 1 - i_hi + (S_ - 1)];
            *(float2*)&Pw[r * PLD + j] = make_float2(acc[0] * 0.125f + r0, acc[1] * 0.125f + r1);
            *(float2*)&Pw[(r + 8) * PLD + j] = make_float2(acc[2] * 0.125f + r2, acc[3] * 0.125f + r3);
        } else {        // j in [200,208): masked
            *(float2*)&Pw[r * PLD + j] = make_float2(-1e30f, -1e30f);
            *(float2*)&Pw[(r + 8) * PLD + j] = make_float2(-1e30f, -1e30f);
        }
    }
    __syncwarp();

    // ---- warp softmax: 2 lanes per row, 104 cols each ----
    {
        const int lr = lane & 15, hh = lane >> 4;
        float* prow = Pw + lr * PLD + hh * 104;
        float4 vv[26];
        float mx = -1e30f;
#pragma unroll
        for (int q = 0; q < 26; q++) {
            vv[q] = *(float4*)&prow[q * 4];
            mx = fmaxf(mx, fmaxf(fmaxf(vv[q].x, vv[q].y), fmaxf(vv[q].z, vv[q].w)));
        }
        mx = fmaxf(mx, __shfl_xor_sync(0xffffffffu, mx, 16));
        float sum = 0.f;
#pragma unroll
        for (int q = 0; q < 26; q++) {
            vv[q].x = __expf(vv[q].x - mx);
            vv[q].y = __expf(vv[q].y - mx);
            vv[q].z = __expf(vv[q].z - mx);
            vv[q].w = __expf(vv[q].w - mx);
            sum += vv[q].x + vv[q].y + vv[q].z + vv[q].w;
        }
        sum += __shfl_xor_sync(0xffffffffu, sum, 16);
        const float inv = 1.f / sum;
#pragma unroll
        for (int q = 0; q < 26; q++) {
            float4 o;
            o.x = vv[q].x * inv; o.y = vv[q].y * inv;
            o.z = vv[q].z * inv; o.w = vv[q].w * inv;
            *(float4*)&prow[q * 4] = cvt4(o);
        }
    }
    __syncwarp();

    // ---- PV: out[16][64] = P[16][208] @ V[208][64] ----
    unsigned int pa[NJT][4];
#pragma unroll
    for (int kt = 0; kt < NJT; kt++) {
        pa[kt][0] = __float_as_uint(Pw[r * PLD + kt * 8 + c]);
        pa[kt][1] = __float_as_uint(Pw[(r + 8) * PLD + kt * 8 + c]);
        pa[kt][2] = __float_as_uint(Pw[r * PLD + kt * 8 + c + 4]);
        pa[kt][3] = __float_as_uint(Pw[(r + 8) * PLD + kt * 8 + c + 4]);
    }
    float* ob = att + ((size_t)b * L_ + (i0 - LT_)) * C_ + h * D_;
#pragma unroll
    for (int nt = 0; nt < 8; nt++) {
        const int d0 = nt * 8;
        float acc[4] = {0.f, 0.f, 0.f, 0.f};
#pragma unroll
        for (int kt = 0; kt < NJT; kt++) {
            unsigned int bfr[2];
            bfr[0] = __float_as_uint(Qs[(kt * 8 + c) * QLD + d0 + r]);
            bfr[1] = __float_as_uint(Qs[(kt * 8 + c + 4) * QLD + d0 + r]);
            mma8(acc, pa[kt], bfr);
        }
        const int dd = d0 + 2 * c;
        *(float2*)&ob[(size_t)r * C_ + dd] = make_float2(acc[0], acc[1]);
        *(float2*)&ob[(size_t)(r + 8) * C_ + dd] = make_float2(acc[2], acc[3]);
    }
}

// ================= residual + layernorm =================
__device__ __forceinline__ float block_sum256(float v, float* red) {
    __syncthreads();
#pragma unroll
    for (int o = 16; o; o >>= 1) v += __shfl_xor_sync(0xffffffffu, v, o);
    int w = threadIdx.x >> 5;
    if ((threadIdx.x & 31) == 0) red[w] = v;
    __syncthreads();
    if (w == 0) {
        float x = ((threadIdx.x & 31) < 8) ? red[threadIdx.x & 31] : 0.f;
#pragma unroll
        for (int o = 4; o; o >>= 1) x += __shfl_xor_sync(0xffffffffu, x, o);
        if (threadIdx.x == 0) red[0] = x;
    }
    __syncthreads();
    return red[0];
}

__global__ __launch_bounds__(256) void k_ln(const float* __restrict__ z,
                                            const float* __restrict__ xa,
                                            const float* __restrict__ gamma,
                                            const float* __restrict__ beta,
                                            float* __restrict__ h2) {
    __shared__ float red[8];
    int m = blockIdx.x;
    int b = m / L_, l = m % L_;
    const float* zr = z + (size_t)m * C_;
    const float* rr = xa + ((size_t)b * S_ + LT_ + l) * C_;
    int t = threadIdx.x;
    float v0 = zr[t] + rr[t];
    float v1 = zr[t + 256] + rr[t + 256];
    float s = block_sum256(v0 + v1, red);
    float mu = s * (1.f / (float)C_);
    float d0 = v0 - mu, d1 = v1 - mu;
    float vs = block_sum256(d0 * d0 + d1 * d1, red);
    float rstd = rsqrtf(vs * (1.f / (float)C_) + 1e-5f);
    h2[(size_t)m * C_ + t] = d0 * rstd * gamma[t] + beta[t];
    h2[(size_t)m * C_ + t + 256] = d1 * rstd * gamma[t + 256] + beta[t + 256];
}

// ================= launch =================
extern "C" void kernel_launch(void* const* d_in, const int* in_sizes, int n_in,
                              void* d_out, int out_size) {
    const float* x         = (const float*)d_in[0];
    const float* text_emb1 = (const float*)d_in[2];
    const float* dw_w      = (const float*)d_in[6];
    const float* dw_b      = (const float*)d_in[7];
    const float* pw_w      = (const float*)d_in[8];
    const float* pw_b      = (const float*)d_in[9];
    const float* wt        = (const float*)d_in[10];
    const float* bt        = (const float*)d_in[11];
    const float* rpe       = (const float*)d_in[12];
    const float* w_out     = (const float*)d_in[13];
    const float* b_out     = (const float*)d_in[14];
    const float* ln_g      = (const float*)d_in[15];
    const float* ln_b      = (const float*)d_in[16];
    const float* wp        = (const float*)d_in[17];
    const float* bp        = (const float*)d_in[18];
    float* out = (float*)d_out;

    float *p_ht, *p_xa, *p_att, *p_z, *p_h2;
    cudaGetSymbolAddress((void**)&p_ht, g_ht);
    cudaGetSymbolAddress((void**)&p_xa, g_xa);
    cudaGetSymbolAddress((void**)&p_att, g_att);
    cudaGetSymbolAddress((void**)&p_z, g_z);
    cudaGetSymbolAddress((void**)&p_h2, g_h2);

    // 1. depthwise + silu -> g_ht (K-major)
    k_dw<<<dim3(C_, B_), 192>>>(x, dw_w, dw_b, p_ht);

    // 2. pointwise GEMM (A K-major) -> xa rows [8,200)
    k_mm<1, 0, 2><<<dim3(4, M_ / BM), 256>>>(p_ht, pw_w, pw_b, p_xa, C_, M_);

    // 3. cond GEMM + silu -> xa rows [0,8)
    k_mm<0, 1, 1><<<dim3(4, 4), 256>>>(text_emb1, wt, bt, p_xa, TD_, TD_);

    // 4. tensor-core attention
    int smem = (SPAD * QLD + 6 * 16 * PLD + (2 * S_ - 1)) * sizeof(float);
    cudaFuncSetAttribute(k_attn_mma, cudaFuncAttributeMaxDynamicSharedMemorySize, smem);
    k_attn_mma<<<dim3(2, H_, B_), 192, smem>>>(p_xa, rpe, p_att);

    // 5. output projection
    k_mm<0, 0, 0><<<dim3(4, M_ / BM), 256>>>(p_att, w_out, b_out, p_z, C_, C_);

    // 6. residual + layernorm
    k_ln<<<B_ * L_, 256>>>(p_z, p_xa, ln_g, ln_b, p_h2);

    // 7. final projection + silu -> out
    k_mm<0, 1, 0><<<dim3(4, M_ / BM), 256>>>(p_h2, wp, bp, out, C_, C_);

    (void)in_sizes; (void)n_in; (void)out_size;
}

// round 7
// speedup vs baseline: 2.9848x; 1.1252x over previous
#include <cuda_runtime.h>
#include <cuda_bf16.h>
#include <math.h>
#include <stdint.h>

// ---------------- problem constants ----------------
#define B_   64
#define L_   192
#define LT_  8
#define S_   200
#define C_   512
#define TD_  768
#define H_   8
#define D_   64
#define J_   22
#define M_   (B_ * L_)   // 12288

// ---------------- scratch ----------------
__device__ float g_ht [C_ * M_];        // depthwise output, K-major: [c][b*192+l]
__device__ float g_xa [B_ * S_ * C_];   // concat [cond(8) ; h(192)] per batch
__device__ float g_att[B_ * L_ * C_];
__device__ float g_z  [B_ * L_ * C_];
__device__ float g_h2 [B_ * L_ * C_];

__device__ __forceinline__ float silu_f(float v) { return v / (1.f + expf(-v)); }

__device__ __forceinline__ unsigned int f2tf32(float f) {
    unsigned int r;
    asm("cvt.rna.tf32.f32 %0, %1;" : "=r"(r) : "f"(f));
    return r;
}
__device__ __forceinline__ float4 cvt4(float4 v) {
    v.x = __uint_as_float(f2tf32(v.x));
    v.y = __uint_as_float(f2tf32(v.y));
    v.z = __uint_as_float(f2tf32(v.z));
    v.w = __uint_as_float(f2tf32(v.w));
    return v;
}
__device__ __forceinline__ void mma8(float* d, const unsigned int* a, const unsigned int* b) {
    asm volatile(
        "mma.sync.aligned.m16n8k8.row.col.f32.tf32.tf32.f32 "
        "{%0,%1,%2,%3}, {%4,%5,%6,%7}, {%8,%9}, {%0,%1,%2,%3};"
        : "+f"(d[0]), "+f"(d[1]), "+f"(d[2]), "+f"(d[3])
        : "r"(a[0]), "r"(a[1]), "r"(a[2]), "r"(a[3]), "r"(b[0]), "r"(b[1]));
}

// ================= kernel 1: depthwise conv + silu, K-major output =================
__global__ __launch_bounds__(192) void k_dw(const float* __restrict__ x,
                                            const float* __restrict__ dw_w,
                                            const float* __restrict__ dw_b,
                                            float* __restrict__ ht) {
    int c = blockIdx.x, b = blockIdx.y, l = threadIdx.x;
    __shared__ float w[J_];
    __shared__ float bias;
    if (threadIdx.x < J_) w[threadIdx.x] = dw_w[c * J_ + threadIdx.x];
    if (threadIdx.x == 0) bias = dw_b[c];
    __syncthreads();
    const float2* xp = (const float2*)(x + (((size_t)b * C_ + c) * L_ + l) * J_);
    float s = bias;
#pragma unroll
    for (int j = 0; j < J_ / 2; j++) {
        float2 v = xp[j];
        s += v.x * w[2 * j] + v.y * w[2 * j + 1];
    }
    ht[(size_t)c * M_ + b * L_ + l] = silu_f(s);
}

// ================= tf32 tensor-core GEMM (unchanged) =================
#define BM 128
#define BN 128
#define BK 32
#define LDA_RM 36
#define LDA_KM 132
#define LDB    36

template <int AKM, int ACT, int OMAP>
__global__ __launch_bounds__(256) void k_mm(const float* __restrict__ A,
                                            const float* __restrict__ W,
                                            const float* __restrict__ bias,
                                            float* __restrict__ out,
                                            int K, int lda) {
    __shared__ float As[BM * LDA_RM];
    __shared__ float Ws[BN * LDB];

    const int tid = threadIdx.x;
    const int lane = tid & 31, wid = tid >> 5;
    const int warp_m = (wid & 1) * 64;
    const int warp_n = (wid >> 1) * 32;
    const int m0 = blockIdx.y * BM, n0 = blockIdx.x * BN;

    float acc[4][4][4];
#pragma unroll
    for (int i = 0; i < 4; i++)
#pragma unroll
        for (int j = 0; j < 4; j++)
#pragma unroll
            for (int r = 0; r < 4; r++) acc[i][j][r] = 0.f;

    const int grow = tid >> 3, gcol = (tid & 7) * 4;
    const int kmc = (tid & 31) * 4, kkr = tid >> 5;

    float4 stA[4], stW[4];
    if (AKM == 0) {
#pragma unroll
        for (int i = 0; i < 4; i++)
            stA[i] = *(const float4*)(A + (size_t)(m0 + grow + 32 * i) * lda + gcol);
    } else {
#pragma unroll
        for (int i = 0; i < 4; i++)
            stA[i] = *(const float4*)(A + (size_t)(kkr + 8 * i) * lda + m0 + kmc);
    }
#pragma unroll
    for (int i = 0; i < 4; i++)
        stW[i] = *(const float4*)(W + (size_t)(n0 + grow + 32 * i) * K + gcol);

    for (int k0 = 0; k0 < K; k0 += BK) {
        __syncthreads();
        if (AKM == 0) {
#pragma unroll
            for (int i = 0; i < 4; i++)
                *(float4*)&As[(grow + 32 * i) * LDA_RM + gcol] = cvt4(stA[i]);
        } else {
#pragma unroll
            for (int i = 0; i < 4; i++)
                *(float4*)&As[(kkr + 8 * i) * LDA_KM + kmc] = cvt4(stA[i]);
        }
#pragma unroll
        for (int i = 0; i < 4; i++)
            *(float4*)&Ws[(grow + 32 * i) * LDB + gcol] = cvt4(stW[i]);
        __syncthreads();

        if (k0 + BK < K) {
            if (AKM == 0) {
#pragma unroll
                for (int i = 0; i < 4; i++)
                    stA[i] = *(const float4*)(A + (size_t)(m0 + grow + 32 * i) * lda + k0 + BK + gcol);
            } else {
#pragma unroll
                for (int i = 0; i < 4; i++)
                    stA[i] = *(const float4*)(A + (size_t)(k0 + BK + kkr + 8 * i) * lda + m0 + kmc);
            }
#pragma unroll
            for (int i = 0; i < 4; i++)
                stW[i] = *(const float4*)(W + (size_t)(n0 + grow + 32 * i) * K + k0 + BK + gcol);
        }

#pragma unroll
        for (int ks = 0; ks < 4; ks++) {
            const int col = ks * 8 + (lane & 3);
            unsigned int afr[4][4], bfr[4][2];
#pragma unroll
            for (int mt = 0; mt < 4; mt++) {
                int row = warp_m + mt * 16 + (lane >> 2);
                if (AKM == 0) {
                    afr[mt][0] = __float_as_uint(As[row * LDA_RM + col]);
                    afr[mt][1] = __float_as_uint(As[(row + 8) * LDA_RM + col]);
                    afr[mt][2] = __float_as_uint(As[row * LDA_RM + col + 4]);
                    afr[mt][3] = __float_as_uint(As[(row + 8) * LDA_RM + col + 4]);
                } else {
                    afr[mt][0] = __float_as_uint(As[col * LDA_KM + row]);
                    afr[mt][1] = __float_as_uint(As[col * LDA_KM + row + 8]);
                    afr[mt][2] = __float_as_uint(As[(col + 4) * LDA_KM + row]);
                    afr[mt][3] = __float_as_uint(As[(col + 4) * LDA_KM + row + 8]);
                }
            }
#pragma unroll
            for (int nt = 0; nt < 4; nt++) {
                int nrow = warp_n + nt * 8 + (lane >> 2);
                bfr[nt][0] = __float_as_uint(Ws[nrow * LDB + col]);
                bfr[nt][1] = __float_as_uint(Ws[nrow * LDB + col + 4]);
            }
#pragma unroll
            for (int mt = 0; mt < 4; mt++)
#pragma unroll
                for (int nt = 0; nt < 4; nt++)
                    mma8(acc[mt][nt], afr[mt], bfr[nt]);
        }
    }

#pragma unroll
    for (int nt = 0; nt < 4; nt++) {
        const int n = n0 + warp_n + nt * 8 + (lane & 3) * 2;
        const float bi0 = bias[n], bi1 = bias[n + 1];
#pragma unroll
        for (int mt = 0; mt < 4; mt++) {
            int m = m0 + warp_m + mt * 16 + (lane >> 2);
#pragma unroll
            for (int half = 0; half < 2; half++) {
                int mm = m + half * 8;
                size_t orow;
                if (OMAP == 0) orow = (size_t)mm;
                else if (OMAP == 1) orow = (size_t)(mm >> 3) * S_ + (mm & 7);
                else orow = (size_t)(mm / L_) * S_ + LT_ + (mm % L_);
                float v0 = acc[mt][nt][half * 2 + 0] + bi0;
                float v1 = acc[mt][nt][half * 2 + 1] + bi1;
                if (ACT == 1) { v0 = silu_f(v0); v1 = silu_f(v1); }
                float2* op = (float2*)(out + orow * C_ + n);
                *op = make_float2(v0, v1);
            }
        }
    }
}

// ================= tensor-core attention, fragment-resident softmax =================
// grid (2, H, B), 192 threads (6 warps), 2 CTAs/SM. Warp owns 16 query rows.
// Scores live in MMA C-fragments; softmax via quad shuffles; P->A frag via shuffles.
#define QLD 68    // 68%32==4 -> conflict-free QK fragment LDS
#define NJT 25    // tiles 0..24 cover j<200 exactly (tile 25 fully masked -> dropped)

__global__ __launch_bounds__(192, 2) void k_attn_mma(const float* __restrict__ xa,
                                                     const float* __restrict__ rpe,
                                                     float* __restrict__ att) {
    extern __shared__ float sm[];
    float* Qs = sm;                 // [200][QLD]
    float* rp = sm + S_ * QLD;      // [399]

    const int half = blockIdx.x, h = blockIdx.y, b = blockIdx.z;
    const int tid = threadIdx.x, lane = tid & 31, w = tid >> 5;
    const int r = lane >> 2, c = lane & 3;

    // stage Q (tf32) + rpe
    {
        const float* base = xa + (size_t)b * S_ * C_ + h * D_;
        int d = tid & 63;
        for (int s = tid >> 6; s < S_; s += 3)
            Qs[s * QLD + d] = __uint_as_float(f2tf32(base[(size_t)s * C_ + d]));
        for (int i = tid; i < 2 * S_ - 1; i += 192) rp[i] = rpe[h * (2 * S_ - 1) + i];
    }
    __syncthreads();

    const int i0 = LT_ + half * 96 + w * 16;
    const int i_lo = i0 + r, i_hi = i_lo + 8;

    // ---- QK^T into register fragments sc[25][4] ----
    unsigned int afr[8][4];
#pragma unroll
    for (int k = 0; k < 8; k++) {
        afr[k][0] = __float_as_uint(Qs[i_lo * QLD + k * 8 + c]);
        afr[k][1] = __float_as_uint(Qs[i_hi * QLD + k * 8 + c]);
        afr[k][2] = __float_as_uint(Qs[i_lo * QLD + k * 8 + c + 4]);
        afr[k][3] = __float_as_uint(Qs[i_hi * QLD + k * 8 + c + 4]);
    }
    float sc[NJT][4];
#pragma unroll
    for (int nt = 0; nt < NJT; nt++) {
        const int j0 = nt * 8;
        float acc[4] = {0.f, 0.f, 0.f, 0.f};
#pragma unroll
        for (int k = 0; k < 8; k++) {
            unsigned int bfr[2];
            bfr[0] = __float_as_uint(Qs[(j0 + r) * QLD + k * 8 + c]);
            bfr[1] = __float_as_uint(Qs[(j0 + r) * QLD + k * 8 + c + 4]);
            mma8(acc, afr[k], bfr);
        }
        const int j = j0 + 2 * c;
        sc[nt][0] = acc[0] * 0.125f + rp[j - i_lo + (S_ - 1)];
        sc[nt][1] = acc[1] * 0.125f + rp[j + 1 - i_lo + (S_ - 1)];
        sc[nt][2] = acc[2] * 0.125f + rp[j - i_hi + (S_ - 1)];
        sc[nt][3] = acc[3] * 0.125f + rp[j + 1 - i_hi + (S_ - 1)];
    }

    // ---- fragment softmax: rows r (elems 0,1) and r+8 (elems 2,3), quad-reduced ----
    {
        float mx0 = -1e30f, mx1 = -1e30f;
#pragma unroll
        for (int nt = 0; nt < NJT; nt++) {
            mx0 = fmaxf(mx0, fmaxf(sc[nt][0], sc[nt][1]));
            mx1 = fmaxf(mx1, fmaxf(sc[nt][2], sc[nt][3]));
        }
        mx0 = fmaxf(mx0, __shfl_xor_sync(0xffffffffu, mx0, 1));
        mx0 = fmaxf(mx0, __shfl_xor_sync(0xffffffffu, mx0, 2));
        mx1 = fmaxf(mx1, __shfl_xor_sync(0xffffffffu, mx1, 1));
        mx1 = fmaxf(mx1, __shfl_xor_sync(0xffffffffu, mx1, 2));
        float s0 = 0.f, s1 = 0.f;
#pragma unroll
        for (int nt = 0; nt < NJT; nt++) {
            sc[nt][0] = __expf(sc[nt][0] - mx0);
            sc[nt][1] = __expf(sc[nt][1] - mx0);
            sc[nt][2] = __expf(sc[nt][2] - mx1);
            sc[nt][3] = __expf(sc[nt][3] - mx1);
            s0 += sc[nt][0] + sc[nt][1];
            s1 += sc[nt][2] + sc[nt][3];
        }
        s0 += __shfl_xor_sync(0xffffffffu, s0, 1);
        s0 += __shfl_xor_sync(0xffffffffu, s0, 2);
        s1 += __shfl_xor_sync(0xffffffffu, s1, 1);
        s1 += __shfl_xor_sync(0xffffffffu, s1, 2);
        const float inv0 = 1.f / s0, inv1 = 1.f / s1;
#pragma unroll
        for (int nt = 0; nt < NJT; nt++) {
            sc[nt][0] = __uint_as_float(f2tf32(sc[nt][0] * inv0));
            sc[nt][1] = __uint_as_float(f2tf32(sc[nt][1] * inv0));
            sc[nt][2] = __uint_as_float(f2tf32(sc[nt][2] * inv1));
            sc[nt][3] = __uint_as_float(f2tf32(sc[nt][3] * inv1));
        }
    }

    // ---- PV: C-frag -> A-frag via quad shuffles, MMA against V (= Q tile) ----
    float acc[8][4];
#pragma unroll
    for (int nt = 0; nt < 8; nt++)
#pragma unroll
        for (int e = 0; e < 4; e++) acc[nt][e] = 0.f;

    const int L0 = (lane & ~3) | (c >> 1);  // quad lane holding cols c (elem c&1)
    const int L1 = L0 + 2;                  // quad lane holding cols c+4
    const bool odd = (c & 1);

#pragma unroll
    for (int kt = 0; kt < NJT; kt++) {
        float v00 = __shfl_sync(0xffffffffu, sc[kt][0], L0);
        float v01 = __shfl_sync(0xffffffffu, sc[kt][1], L0);
        float v10 = __shfl_sync(0xffffffffu, sc[kt][0], L1);
        float v11 = __shfl_sync(0xffffffffu, sc[kt][1], L1);
        float w00 = __shfl_sync(0xffffffffu, sc[kt][2], L0);
        float w01 = __shfl_sync(0xffffffffu, sc[kt][3], L0);
        float w10 = __shfl_sync(0xffffffffu, sc[kt][2], L1);
        float w11 = __shfl_sync(0xffffffffu, sc[kt][3], L1);
        unsigned int pa[4];
        pa[0] = __float_as_uint(odd ? v01 : v00);  // P[r][kt*8+c]
        pa[1] = __float_as_uint(odd ? w01 : w00);  // P[r+8][kt*8+c]
        pa[2] = __float_as_uint(odd ? v11 : v10);  // P[r][kt*8+c+4]
        pa[3] = __float_as_uint(odd ? w11 : w10);  // P[r+8][kt*8+c+4]
        const int kr0 = (kt * 8 + c) * QLD, kr1 = (kt * 8 + c + 4) * QLD;
#pragma unroll
        for (int nt = 0; nt < 8; nt++) {
            unsigned int bfr[2];
            bfr[0] = __float_as_uint(Qs[kr0 + nt * 8 + r]);
            bfr[1] = __float_as_uint(Qs[kr1 + nt * 8 + r]);
            mma8(acc[nt], pa, bfr);
        }
    }

    float* ob = att + ((size_t)b * L_ + (i0 - LT_)) * C_ + h * D_;
#pragma unroll
    for (int nt = 0; nt < 8; nt++) {
        const int dd = nt * 8 + 2 * c;
        *(float2*)&ob[(size_t)r * C_ + dd] = make_float2(acc[nt][0], acc[nt][1]);
        *(float2*)&ob[(size_t)(r + 8) * C_ + dd] = make_float2(acc[nt][2], acc[nt][3]);
    }
}

// ================= residual + layernorm =================
__device__ __forceinline__ float block_sum256(float v, float* red) {
    __syncthreads();
#pragma unroll
    for (int o = 16; o; o >>= 1) v += __shfl_xor_sync(0xffffffffu, v, o);
    int w = threadIdx.x >> 5;
    if ((threadIdx.x & 31) == 0) red[w] = v;
    __syncthreads();
    if (w == 0) {
        float x = ((threadIdx.x & 31) < 8) ? red[threadIdx.x & 31] : 0.f;
#pragma unroll
        for (int o = 4; o; o >>= 1) x += __shfl_xor_sync(0xffffffffu, x, o);
        if (threadIdx.x == 0) red[0] = x;
    }
    __syncthreads();
    return red[0];
}

__global__ __launch_bounds__(256) void k_ln(const float* __restrict__ z,
                                            const float* __restrict__ xa,
                                            const float* __restrict__ gamma,
                                            const float* __restrict__ beta,
                                            float* __restrict__ h2) {
    __shared__ float red[8];
    int m = blockIdx.x;
    int b = m / L_, l = m % L_;
    const float* zr = z + (size_t)m * C_;
    const float* rr = xa + ((size_t)b * S_ + LT_ + l) * C_;
    int t = threadIdx.x;
    float v0 = zr[t] + rr[t];
    float v1 = zr[t + 256] + rr[t + 256];
    float s = block_sum256(v0 + v1, red);
    float mu = s * (1.f / (float)C_);
    float d0 = v0 - mu, d1 = v1 - mu;
    float vs = block_sum256(d0 * d0 + d1 * d1, red);
    float rstd = rsqrtf(vs * (1.f / (float)C_) + 1e-5f);
    h2[(size_t)m * C_ + t] = d0 * rstd * gamma[t] + beta[t];
    h2[(size_t)m * C_ + t + 256] = d1 * rstd * gamma[t + 256] + beta[t + 256];
}

// ================= launch =================
extern "C" void kernel_launch(void* const* d_in, const int* in_sizes, int n_in,
                              void* d_out, int out_size) {
    const float* x         = (const float*)d_in[0];
    const float* text_emb1 = (const float*)d_in[2];
    const float* dw_w      = (const float*)d_in[6];
    const float* dw_b      = (const float*)d_in[7];
    const float* pw_w      = (const float*)d_in[8];
    const float* pw_b      = (const float*)d_in[9];
    const float* wt        = (const float*)d_in[10];
    const float* bt        = (const float*)d_in[11];
    const float* rpe       = (const float*)d_in[12];
    const float* w_out     = (const float*)d_in[13];
    const float* b_out     = (const float*)d_in[14];
    const float* ln_g      = (const float*)d_in[15];
    const float* ln_b      = (const float*)d_in[16];
    const float* wp        = (const float*)d_in[17];
    const float* bp        = (const float*)d_in[18];
    float* out = (float*)d_out;

    float *p_ht, *p_xa, *p_att, *p_z, *p_h2;
    cudaGetSymbolAddress((void**)&p_ht, g_ht);
    cudaGetSymbolAddress((void**)&p_xa, g_xa);
    cudaGetSymbolAddress((void**)&p_att, g_att);
    cudaGetSymbolAddress((void**)&p_z, g_z);
    cudaGetSymbolAddress((void**)&p_h2, g_h2);

    // 1. depthwise + silu -> g_ht (K-major)
    k_dw<<<dim3(C_, B_), 192>>>(x, dw_w, dw_b, p_ht);

    // 2. pointwise GEMM (A K-major) -> xa rows [8,200)
    k_mm<1, 0, 2><<<dim3(4, M_ / BM), 256>>>(p_ht, pw_w, pw_b, p_xa, C_, M_);

    // 3. cond GEMM + silu -> xa rows [0,8)
    k_mm<0, 1, 1><<<dim3(4, 4), 256>>>(text_emb1, wt, bt, p_xa, TD_, TD_);

    // 4. tensor-core attention (fragment-resident softmax)
    int smem = (S_ * QLD + (2 * S_ - 1)) * sizeof(float);
    cudaFuncSetAttribute(k_attn_mma, cudaFuncAttributeMaxDynamicSharedMemorySize, smem);
    k_attn_mma<<<dim3(2, H_, B_), 192, smem>>>(p_xa, rpe, p_att);

    // 5. output projection
    k_mm<0, 0, 0><<<dim3(4, M_ / BM), 256>>>(p_att, w_out, b_out, p_z, C_, C_);

    // 6. residual + layernorm
    k_ln<<<B_ * L_, 256>>>(p_z, p_xa, ln_g, ln_b, p_h2);

    // 7. final projection + silu -> out
    k_mm<0, 1, 0><<<dim3(4, M_ / BM), 256>>>(p_h2, wp, bp, out, C_, C_);

    (void)in_sizes; (void)n_in; (void)out_size;
}